// round 12
// baseline (speedup 1.0000x reference)
#include <cuda_runtime.h>
#include <math.h>

// Shapes (hardcoded from reference setup_inputs)
#define Bn   64
#define Nn   1025
#define Dn   1024
#define Cn   64
#define TOT  (Bn * Nn)   // 65600 rows

// Scratch (device globals; no runtime allocation)
__device__ __align__(16) float g_h[(size_t)TOT * Cn];         // post LN+GEMM1   (B,N,C)
__device__ __align__(16) float g_sp[(size_t)Bn * 1024 * Cn];  // post depthwise  (B,HW,C)
__device__ __align__(16) float g_act[(size_t)TOT * Cn];       // post proj+gelu  (B,N,C)
__device__ __align__(16) float g_part[2][(size_t)TOT * Cn];   // GEMM1 k-half partials
__device__ __align__(8)  float2 g_stats[TOT];                 // per-row (mu, rsigma)

// ---------- packed f32x2 helpers ----------
static __device__ __forceinline__ unsigned long long pk2(float a, float b) {
    unsigned long long r;
    asm("mov.b64 %0, {%1,%2};" : "=l"(r) : "f"(a), "f"(b));
    return r;
}
static __device__ __forceinline__ void upk2(unsigned long long v, float& a, float& b) {
    asm("mov.b64 {%0,%1}, %2;" : "=f"(a), "=f"(b) : "l"(v));
}
static __device__ __forceinline__ void fma2(unsigned long long& d, unsigned long long a,
                                            unsigned long long b) {
    asm("fma.rn.f32x2 %0, %1, %2, %0;" : "+l"(d) : "l"(a), "l"(b));
}
static __device__ __forceinline__ void add2(unsigned long long& d, unsigned long long a) {
    asm("add.rn.f32x2 %0, %0, %1;" : "+l"(d) : "l"(a));
}

static __device__ __forceinline__ float gelu_exact(float t) {
    return 0.5f * t * (1.0f + erff(t * 0.70710678118654752f));
}

// ======================================================================
// Kernel 0: per-row LayerNorm stats (mu, rsigma). One warp per row.
// ======================================================================
__global__ __launch_bounds__(256) void k0_stats(const float* __restrict__ x)
{
    const int row = blockIdx.x * 8 + (threadIdx.x >> 5);
    const int l = threadIdx.x & 31;
    const int b = row / Nn, n = row - b * Nn;
    const float4* p = (const float4*)(x + ((size_t)(n * Bn + b) << 10));
    float s = 0.f, q = 0.f;
#pragma unroll
    for (int i = 0; i < 8; i++) {
        float4 t = p[l + 32 * i];
        s += t.x + t.y + t.z + t.w;
        q += t.x * t.x + t.y * t.y + t.z * t.z + t.w * t.w;
    }
#pragma unroll
    for (int o = 16; o; o >>= 1) {
        s += __shfl_xor_sync(0xffffffffu, s, o);
        q += __shfl_xor_sync(0xffffffffu, q, o);
    }
    if (l == 0) {
        float mu = s * (1.0f / 1024.0f);
        float var = q * (1.0f / 1024.0f) - mu * mu;
        g_stats[row] = make_float2(mu, rsqrtf(var + 1e-5f));
    }
}

// ======================================================================
// Kernel 1s: streaming LN+GEMM1 with smem-resident weight k-half.
// grid = 65 row-blocks x 2 k-halves. Block: w1 half [512k][64c] = 128KB
// loaded ONCE; streams 1024 rows in 16 subtiles of 64 rows. Per subtile,
// 2 rounds of 256k: produce y (LN fused, stats precomputed) into
// ys[256][68], then f32x2 GEMM with 4-way k-split; partials reduced via
// add.rn.f32x2 in smem; result -> g_part[h]. Weight L2: 2.1GB -> 17MB.
// ======================================================================
#define K1S_SMEM (512*64*4 + 256*68*4)

__global__ __launch_bounds__(512, 1) void k1s_gemm1(
    const float* __restrict__ x, const float* __restrict__ lnw, const float* __restrict__ lnb,
    const float* __restrict__ gam, const float* __restrict__ gmx,
    const float* __restrict__ w1)
{
    extern __shared__ __align__(16) char smc[];
    float* ws = (float*)smc;                       // [512][64]
    float* ys = (float*)(smc + 512 * 64 * 4);      // [256][68] (padded stride)

    const int tid = threadIdx.x;
    const int h = blockIdx.x & 1;                  // k-half
    const int rb = blockIdx.x >> 1;                // row block
    const int rowbase = rb << 10;
    const int rem = (TOT - rowbase) >> 6;
    const int nsub = rem < 16 ? rem : 16;

    // ---- load weight half (contiguous 128KB, once) ----
    {
        const float4* wsrc = (const float4*)(w1 + (size_t)h * 512 * 64);
        float4* wdst = (float4*)ws;
#pragma unroll
        for (int i = 0; i < 16; i++)
            wdst[tid + 512 * i] = wsrc[tid + 512 * i];
    }

    // produce role: row pr (0..63), k-chunk pq (32 k each)
    const int pr = tid & 63, pq = tid >> 6;
    // GEMM role: ks = k-split group, rg = 8-row group, cg = 4-col group
    const int ks = tid >> 7;
    const int rg = (tid >> 4) & 7;
    const int cg = tid & 15;
    const int t2 = tid & 127;

    for (int s = 0; s < nsub; s++) {
        const int prow = rowbase + s * 64 + pr;
        const int pb = prow / Nn, pn = prow - pb * Nn;
        const float* xr = x + ((size_t)(pn * Bn + pb) << 10) + h * 512;
        const float2 st = g_stats[prow];
        const float pmu = st.x, prs = st.y;

        unsigned long long acc[4][4];
#pragma unroll
        for (int p = 0; p < 4; p++)
#pragma unroll
            for (int jc = 0; jc < 4; jc++) acc[p][jc] = 0ull;

        for (int j = 0; j < 2; j++) {
            __syncthreads();   // weights ready / prev round reads done

            // ---- produce y for k in [j*256, j*256+256) of this half ----
#pragma unroll
            for (int i = 0; i < 8; i++) {
                const int kl = pq * 32 + i * 4;
                float4 xv = *(const float4*)(xr + j * 256 + kl);
                const int f4 = (h * 512 + j * 256 + kl) >> 2;
                float4 lw = ((const float4*)lnw)[f4];
                float4 lb = ((const float4*)lnb)[f4];
                float4 gm = ((const float4*)gam)[f4];
                float4 gx = ((const float4*)gmx)[f4];
                float y0 = ((xv.x - pmu) * prs * lw.x + lb.x) * gm.x + xv.x * gx.x;
                float y1 = ((xv.y - pmu) * prs * lw.y + lb.y) * gm.y + xv.y * gx.y;
                float y2 = ((xv.z - pmu) * prs * lw.z + lb.z) * gm.z + xv.z * gx.z;
                float y3 = ((xv.w - pmu) * prs * lw.w + lb.w) * gm.w + xv.w * gx.w;
                ys[(kl + 0) * 68 + pr] = y0;
                ys[(kl + 1) * 68 + pr] = y1;
                ys[(kl + 2) * 68 + pr] = y2;
                ys[(kl + 3) * 68 + pr] = y3;
            }
            __syncthreads();

            // ---- GEMM over this ks-group's 64 k ----
            const float* wsj = ws + (j * 256 + ks * 64) * 64;
            const float* ysj = ys + (ks * 64) * 68;
#pragma unroll 4
            for (int kk = 0; kk < 64; kk++) {
                ulonglong2 yA = *(const ulonglong2*)(ysj + kk * 68 + rg * 8);
                ulonglong2 yB = *(const ulonglong2*)(ysj + kk * 68 + rg * 8 + 4);
                float4 w = *(const float4*)(wsj + kk * 64 + cg * 4);
                unsigned long long w0 = pk2(w.x, w.x), w1d = pk2(w.y, w.y);
                unsigned long long w2d = pk2(w.z, w.z), w3d = pk2(w.w, w.w);
                fma2(acc[0][0], yA.x, w0); fma2(acc[0][1], yA.x, w1d);
                fma2(acc[0][2], yA.x, w2d); fma2(acc[0][3], yA.x, w3d);
                fma2(acc[1][0], yA.y, w0); fma2(acc[1][1], yA.y, w1d);
                fma2(acc[1][2], yA.y, w2d); fma2(acc[1][3], yA.y, w3d);
                fma2(acc[2][0], yB.x, w0); fma2(acc[2][1], yB.x, w1d);
                fma2(acc[2][2], yB.x, w2d); fma2(acc[2][3], yB.x, w3d);
                fma2(acc[3][0], yB.y, w0); fma2(acc[3][1], yB.y, w1d);
                fma2(acc[3][2], yB.y, w2d); fma2(acc[3][3], yB.y, w3d);
            }
        }

        // ---- k-split reduction (alias ys; 48KB needed, 68KB available) ----
        __syncthreads();
        unsigned long long* redu = (unsigned long long*)ys;
        if (ks) {
#pragma unroll
            for (int p = 0; p < 4; p++)
#pragma unroll
                for (int jc = 0; jc < 4; jc++)
                    redu[((ks - 1) * 128 + t2) * 16 + p * 4 + jc] = acc[p][jc];
        }
        __syncthreads();
        if (!ks) {
#pragma unroll
            for (int p = 0; p < 4; p++) {
                float ae[4], ao[4];
#pragma unroll
                for (int jc = 0; jc < 4; jc++) {
#pragma unroll
                    for (int g = 0; g < 3; g++)
                        add2(acc[p][jc], redu[(g * 128 + t2) * 16 + p * 4 + jc]);
                    upk2(acc[p][jc], ae[jc], ao[jc]);
                }
                const int rowe = rowbase + s * 64 + rg * 8 + 2 * p;
                float* de = &g_part[h][(size_t)rowe * 64 + cg * 4];
                *(float4*)de = make_float4(ae[0], ae[1], ae[2], ae[3]);
                *(float4*)(de + 64) = make_float4(ao[0], ao[1], ao[2], ao[3]);
            }
        }
        // next iteration's leading __syncthreads protects redu/ys reuse
    }
}

// ======================================================================
// Kernel 5: g_h = g_part[0] + g_part[1] + b1
// ======================================================================
__global__ __launch_bounds__(256) void k5_reduce(const float* __restrict__ b1)
{
    const int i4 = blockIdx.x * 256 + threadIdx.x;   // float4 index, 1,049,600 total
    float4 a = ((const float4*)g_part[0])[i4];
    float4 b = ((const float4*)g_part[1])[i4];
    float4 bb = ((const float4*)b1)[i4 & 15];
    ((float4*)g_h)[i4] = make_float4(a.x + b.x + bb.x, a.y + b.y + bb.y,
                                     a.z + b.z + bb.z, a.w + b.w + bb.w);
}

// ======================================================================
// Kernel 2: depthwise 3x3 + 5x5 + 7x7, averaged, + identity -> g_sp
// ======================================================================
__global__ __launch_bounds__(256) void k2_dwconv(
    const float* __restrict__ w3, const float* __restrict__ b3,
    const float* __restrict__ w5, const float* __restrict__ b5,
    const float* __restrict__ w7, const float* __restrict__ b7)
{
    __shared__ __align__(16) float tile[38 * 38 * 4];
    __shared__ float wk[4 * 83];

    const int tid = threadIdx.x;
    const int cg = blockIdx.x;
    const int b = blockIdx.y;

    for (int i = tid; i < 4 * 83; i += 256) {
        int ch = i / 83, j = i - ch * 83;
        int c = cg * 4 + ch;
        float wv;
        if (j < 9)       wv = w3[c * 9 + j];
        else if (j < 34) wv = w5[c * 25 + (j - 9)];
        else             wv = w7[c * 49 + (j - 34)];
        wk[i] = wv;
    }

    const float* src = g_h + ((size_t)b * Nn + 1) * 64 + cg * 4;
    for (int idx = tid; idx < 38 * 38; idx += 256) {
        int rr = idx / 38, cc = idx - rr * 38;
        int gy = rr - 3, gx = cc - 3;
        float4 val = make_float4(0.f, 0.f, 0.f, 0.f);
        if ((unsigned)gy < 32u && (unsigned)gx < 32u)
            val = *(const float4*)(src + (size_t)(gy * 32 + gx) * 64);
        *(float4*)&tile[idx * 4] = val;
    }
    __syncthreads();

    const int ch = tid & 3;
    const int col = (tid >> 2) & 31;
    const int row0 = (tid >> 7) * 16;

    float acc[16];
#pragma unroll
    for (int k = 0; k < 16; k++) acc[k] = 0.f;

    const float* wc = wk + ch * 83;

#define CONV_TAPS(RAD, WOFF, KS)                                                   \
    for (int dy = -(RAD); dy <= (RAD); dy++) {                                     \
        for (int dx = -(RAD); dx <= (RAD); dx++) {                                 \
            float wv = wc[(WOFF) + (dy + (RAD)) * (KS) + (dx + (RAD))];            \
            const float* tp = tile + (((row0 + 3 + dy) * 38) + (col + 3 + dx)) * 4 + ch; \
            _Pragma("unroll")                                                      \
            for (int k = 0; k < 16; k++) acc[k] += tp[k * 152] * wv;               \
        }                                                                          \
    }

    CONV_TAPS(1, 0, 3)
    CONV_TAPS(2, 9, 5)
    CONV_TAPS(3, 34, 7)
#undef CONV_TAPS

    const int c = cg * 4 + ch;
    const float bsum = (b3[c] + b5[c] + b7[c]) * (1.0f / 3.0f);
    float* dst = g_sp + ((size_t)b * 1024) * 64 + c;
    const float* ctr = tile + ((row0 + 3) * 38 + col + 3) * 4 + ch;
#pragma unroll
    for (int k = 0; k < 16; k++) {
        float o = acc[k] * (1.0f / 3.0f) + bsum + ctr[k * 152];
        dst[(size_t)((row0 + k) * 32 + col) * 64] = o;
    }
}

// ======================================================================
// Kernel 3: 1x1 proj + residual + exact GELU -> g_act (spatial tokens)
// ======================================================================
__global__ __launch_bounds__(256) void k3_proj_gelu(
    const float* __restrict__ pw, const float* __restrict__ pb)
{
    __shared__ float pws[64 * 65];
    __shared__ float ssp[32 * 64];

    const int tid = threadIdx.x;
    const int b = blockIdx.x >> 5;
    const int pbase = (blockIdx.x & 31) * 32;

    for (int i = tid; i < 4096; i += 256)
        pws[(i >> 6) * 65 + (i & 63)] = pw[i];

    const float* src = g_sp + ((size_t)b * 1024 + pbase) * 64;
    for (int i = tid; i < 2048; i += 256) ssp[i] = src[i];
    __syncthreads();

    const int c = tid & 63;
    const int pg = tid >> 6;
    float acc[8];
#pragma unroll
    for (int j = 0; j < 8; j++) acc[j] = 0.f;

    const float* wr = pws + c * 65;
    const float* sr = ssp + pg * 8 * 64;
#pragma unroll 8
    for (int k = 0; k < 64; k++) {
        float wv = wr[k];
#pragma unroll
        for (int j = 0; j < 8; j++) acc[j] += sr[j * 64 + k] * wv;
    }

    const float pbv = pb[c];
    float* dst = g_act + ((size_t)b * Nn + 1 + pbase + pg * 8) * 64 + c;
#pragma unroll
    for (int j = 0; j < 8; j++) {
        float t = sr[j * 64 + c] + acc[j] + pbv;
        dst[(size_t)j * 64] = gelu_exact(t);
    }
}

// CLS token: gelu only
__global__ void k_cls_gelu() {
    int i = blockIdx.x * 256 + threadIdx.x;
    if (i < Bn * Cn) {
        int b = i >> 6, c = i & 63;
        size_t off = (size_t)b * Nn * 64 + c;
        g_act[off] = gelu_exact(g_h[off]);
    }
}

// ======================================================================
// Kernel 4: GEMM2 (g_act @ w2 + b2) + residual x -> out
// Block = 128-col chunk of w2 resident in smem (32KB, loaded ONCE),
// streams 512 rows in 8 subtiles of 64.
// ======================================================================
#define K4_SMEM (64*128*4 + 64*64*4)

__global__ __launch_bounds__(256, 3) void k4_gemm2(
    const float* __restrict__ x, const float* __restrict__ w2,
    const float* __restrict__ b2, float* __restrict__ out)
{
    extern __shared__ __align__(16) char sm4[];
    float* w2s = (float*)sm4;                      // [64 k][128 c]
    float* sga = (float*)(sm4 + 64 * 128 * 4);     // [64 k][64 r]

    const int tid = threadIdx.x;
    const int rb = blockIdx.x >> 3;
    const int co = (blockIdx.x & 7) * 128;
    const int rowbase = rb * 512;
    const int nsub = (TOT - rowbase < 512) ? ((TOT - rowbase) >> 6) : 8;

#pragma unroll
    for (int i = 0; i < 8; i++) {
        int f = tid + 256 * i;
        int k = f >> 5, c4 = f & 31;
        ((float4*)w2s)[f] = *(const float4*)(w2 + (size_t)k * 1024 + co + c4 * 4);
    }

    const int rg = tid >> 5;
    const int cw = tid & 31;
    const int c0g = co + cw * 4;
    const float4 bv = *(const float4*)(b2 + c0g);

    const int lr = tid >> 2;
    const int lq = tid & 3;

    for (int s2 = 0; s2 < nsub; s2++) {
        __syncthreads();

        {
            int row = rowbase + s2 * 64 + lr;
            int b = row / Nn, n = row - b * Nn;
            const float4* gp = (const float4*)(g_act + ((size_t)b * Nn + n) * 64 + lq * 16);
#pragma unroll
            for (int i = 0; i < 4; i++) {
                float4 g = gp[i];
                int k0 = lq * 16 + i * 4;
                sga[(k0 + 0) * 64 + lr] = g.x;
                sga[(k0 + 1) * 64 + lr] = g.y;
                sga[(k0 + 2) * 64 + lr] = g.z;
                sga[(k0 + 3) * 64 + lr] = g.w;
            }
        }
        __syncthreads();

        unsigned long long acc[4][4];
#pragma unroll
        for (int p = 0; p < 4; p++)
#pragma unroll
            for (int j = 0; j < 4; j++) acc[p][j] = 0ull;

#pragma unroll 4
        for (int k = 0; k < 64; k++) {
            ulonglong2 yA = *(const ulonglong2*)(sga + (k << 6) + (rg << 3));
            ulonglong2 yB = *(const ulonglong2*)(sga + (k << 6) + (rg << 3) + 4);
            float4 w = *(const float4*)(w2s + (k << 7) + (cw << 2));
            unsigned long long w0 = pk2(w.x, w.x), w1d = pk2(w.y, w.y);
            unsigned long long w2d = pk2(w.z, w.z), w3 = pk2(w.w, w.w);
            fma2(acc[0][0], yA.x, w0); fma2(acc[0][1], yA.x, w1d);
            fma2(acc[0][2], yA.x, w2d); fma2(acc[0][3], yA.x, w3);
            fma2(acc[1][0], yA.y, w0); fma2(acc[1][1], yA.y, w1d);
            fma2(acc[1][2], yA.y, w2d); fma2(acc[1][3], yA.y, w3);
            fma2(acc[2][0], yB.x, w0); fma2(acc[2][1], yB.x, w1d);
            fma2(acc[2][2], yB.x, w2d); fma2(acc[2][3], yB.x, w3);
            fma2(acc[3][0], yB.y, w0); fma2(acc[3][1], yB.y, w1d);
            fma2(acc[3][2], yB.y, w2d); fma2(acc[3][3], yB.y, w3);
        }

#pragma unroll
        for (int p = 0; p < 4; p++) {
            int rowe = rowbase + s2 * 64 + rg * 8 + 2 * p;
            float ae[4], ao[4];
#pragma unroll
            for (int j = 0; j < 4; j++) upk2(acc[p][j], ae[j], ao[j]);

            int b = rowe / Nn, n = rowe - b * Nn;
            size_t offe = ((size_t)(n * Bn + b) << 10) + c0g;
            float4 xe = *(const float4*)(x + offe);
            *(float4*)(out + offe) = make_float4(xe.x + bv.x + ae[0], xe.y + bv.y + ae[1],
                                                 xe.z + bv.z + ae[2], xe.w + bv.w + ae[3]);
            int rowo = rowe + 1;
            int b2i = rowo / Nn, n2 = rowo - b2i * Nn;
            size_t offo = ((size_t)(n2 * Bn + b2i) << 10) + c0g;
            float4 xo = *(const float4*)(x + offo);
            *(float4*)(out + offo) = make_float4(xo.x + bv.x + ao[0], xo.y + bv.y + ao[1],
                                                 xo.z + bv.z + ao[2], xo.w + bv.w + ao[3]);
        }
    }
}

// ======================================================================
extern "C" void kernel_launch(void* const* d_in, const int* in_sizes, int n_in,
                              void* d_out, int out_size)
{
    (void)in_sizes; (void)n_in; (void)out_size;
    const float* x     = (const float*)d_in[0];
    const float* ln_w  = (const float*)d_in[1];
    const float* ln_b  = (const float*)d_in[2];
    const float* gamma = (const float*)d_in[3];
    const float* gmx   = (const float*)d_in[4];
    const float* w1    = (const float*)d_in[5];
    const float* b1    = (const float*)d_in[6];
    const float* w2    = (const float*)d_in[7];
    const float* b2    = (const float*)d_in[8];
    const float* dw3w  = (const float*)d_in[9];
    const float* dw3b  = (const float*)d_in[10];
    const float* dw5w  = (const float*)d_in[11];
    const float* dw5b  = (const float*)d_in[12];
    const float* dw7w  = (const float*)d_in[13];
    const float* dw7b  = (const float*)d_in[14];
    const float* projw = (const float*)d_in[15];
    const float* projb = (const float*)d_in[16];
    float* out = (float*)d_out;

    cudaFuncSetAttribute(k1s_gemm1, cudaFuncAttributeMaxDynamicSharedMemorySize, K1S_SMEM);
    cudaFuncSetAttribute(k4_gemm2,  cudaFuncAttributeMaxDynamicSharedMemorySize, K4_SMEM);

    k0_stats<<<8200, 256>>>(x);
    // 65 row-blocks (1024 rows; last has 64) x 2 k-halves
    k1s_gemm1<<<130, 512, K1S_SMEM>>>(x, ln_w, ln_b, gamma, gmx, w1);
    k5_reduce<<<4100, 256>>>(b1);
    k2_dwconv<<<dim3(16, 64), 256>>>(dw3w, dw3b, dw5w, dw5b, dw7w, dw7b);
    k_cls_gelu<<<16, 256>>>();
    k3_proj_gelu<<<2048, 256>>>(projw, projb);
    // 129 row-blocks of 512 rows (last has 64) x 8 col-chunks
    k4_gemm2<<<129 * 8, 256, K4_SMEM>>>(x, w2, b2, out);
}

// round 13
// speedup vs baseline: 1.2681x; 1.2681x over previous
#include <cuda_runtime.h>
#include <math.h>

// Shapes (hardcoded from reference setup_inputs)
#define Bn   64
#define Nn   1025
#define Dn   1024
#define Cn   64
#define TOT  (Bn * Nn)   // 65600 rows

// Scratch (device globals; no runtime allocation)
__device__ __align__(16) float g_h[(size_t)TOT * Cn];         // post LN+GEMM1   (B,N,C)
__device__ __align__(16) float g_sp[(size_t)Bn * 1024 * Cn];  // post depthwise  (B,HW,C)
__device__ __align__(16) float g_act[(size_t)TOT * Cn];       // post proj+gelu  (B,N,C)

// ---------- packed f32x2 helpers ----------
static __device__ __forceinline__ unsigned long long pk2(float a, float b) {
    unsigned long long r;
    asm("mov.b64 %0, {%1,%2};" : "=l"(r) : "f"(a), "f"(b));
    return r;
}
static __device__ __forceinline__ void upk2(unsigned long long v, float& a, float& b) {
    asm("mov.b64 {%0,%1}, %2;" : "=f"(a), "=f"(b) : "l"(v));
}
static __device__ __forceinline__ void fma2(unsigned long long& d, unsigned long long a,
                                            unsigned long long b) {
    asm("fma.rn.f32x2 %0, %1, %2, %0;" : "+l"(d) : "l"(a), "l"(b));
}

static __device__ __forceinline__ float gelu_exact(float t) {
    return 0.5f * t * (1.0f + erff(t * 0.70710678118654752f));
}

// ======================================================================
// Kernel 1: LayerNorm + gamma-mix + GEMM1 (y @ w1 + b1) -> g_h
// 12 rows per block, 256 threads, 2 CTAs/SM (96KB smem each).
// Same single-produce / single-GEMM structure as the proven 8-row version;
// produce phase split into 2 halves of 6 rows to bound register pressure.
// ======================================================================
#define K1_SMEM (12 * 1024 * 8)

__global__ __launch_bounds__(256, 2) void k1_ln_gemm1(
    const float* __restrict__ x, const float* __restrict__ lnw, const float* __restrict__ lnb,
    const float* __restrict__ gam, const float* __restrict__ gmx,
    const float* __restrict__ w1, const float* __restrict__ b1)
{
    extern __shared__ __align__(16) char sm1[];
    unsigned long long* syd = (unsigned long long*)sm1;   // [12][1024]
    __shared__ float2 redst[12][8];

    const int tid = threadIdx.x;
    const int warp = tid >> 5, lane = tid & 31;
    const int row0 = blockIdx.x * 12;

    const float4 lw = ((const float4*)lnw)[tid];
    const float4 lb = ((const float4*)lnb)[tid];
    const float4 gm = ((const float4*)gam)[tid];
    const float4 gx = ((const float4*)gmx)[tid];

    // ---- produce in two halves of 6 rows ----
#pragma unroll
    for (int half = 0; half < 2; half++) {
        float4 v[6];
        float s[6], q[6];
#pragma unroll
        for (int r = 0; r < 6; r++) {
            int row = row0 + half * 6 + r;
            row = row < TOT ? row : TOT - 1;            // clamp tail (stats discarded)
            int b = row / Nn, n = row - b * Nn;
            float4 t = ((const float4*)(x + ((size_t)(n * Bn + b) << 10)))[tid];
            v[r] = t;
            s[r] = t.x + t.y + t.z + t.w;
            q[r] = t.x * t.x + t.y * t.y + t.z * t.z + t.w * t.w;
        }
#pragma unroll
        for (int o = 16; o; o >>= 1) {
#pragma unroll
            for (int r = 0; r < 6; r++) {
                s[r] += __shfl_xor_sync(0xffffffffu, s[r], o);
                q[r] += __shfl_xor_sync(0xffffffffu, q[r], o);
            }
        }
        if (lane == 0) {
#pragma unroll
            for (int r = 0; r < 6; r++) redst[half * 6 + r][warp] = make_float2(s[r], q[r]);
        }
        __syncthreads();

#pragma unroll
        for (int r = 0; r < 6; r++) {
            float a = 0.f, c = 0.f;
#pragma unroll
            for (int w = 0; w < 8; w++) {
                float2 t = redst[half * 6 + r][w];
                a += t.x; c += t.y;
            }
            const float mu = a * (1.0f / 1024.0f);
            const float var = c * (1.0f / 1024.0f) - mu * mu;
            const float rs = rsqrtf(var + 1e-5f);
            float4 t = v[r];
            float y0 = ((t.x - mu) * rs * lw.x + lb.x) * gm.x + t.x * gx.x;
            float y1 = ((t.y - mu) * rs * lw.y + lb.y) * gm.y + t.y * gx.y;
            float y2 = ((t.z - mu) * rs * lw.z + lb.z) * gm.z + t.z * gx.z;
            float y3 = ((t.w - mu) * rs * lw.w + lb.w) * gm.w + t.w * gx.w;
            ulonglong2* dst = (ulonglong2*)(syd + (half * 6 + r) * 1024 + tid * 4);
            ulonglong2 d0; d0.x = pk2(y0, y0); d0.y = pk2(y1, y1);
            ulonglong2 d1; d1.x = pk2(y2, y2); d1.y = pk2(y3, y3);
            dst[0] = d0;
            dst[1] = d1;
        }
    }
    __syncthreads();

    // ---- GEMM: thread = (64-d kgroup) x (4 cols) x 12 rows ----
    const int gidx = tid >> 4;       // 0..15 -> d in [gidx*64, +64)
    const int cq = tid & 15;         // cols cq*4..+3
    const int c0 = cq * 4;
    unsigned long long acc[12][2];
#pragma unroll
    for (int r = 0; r < 12; r++) { acc[r][0] = 0ull; acc[r][1] = 0ull; }

    const float4* w1p = (const float4*)w1;
    const int dbase = gidx * 64;
#pragma unroll 4
    for (int dd = 0; dd < 64; dd++) {
        const int d = dbase + dd;
        float4 w = w1p[d * 16 + cq];
        unsigned long long wl = pk2(w.x, w.y), wh = pk2(w.z, w.w);
#pragma unroll
        for (int r = 0; r < 12; r++) {
            unsigned long long yy = syd[r * 1024 + d];
            fma2(acc[r][0], yy, wl);
            fma2(acc[r][1], yy, wh);
        }
    }
    __syncthreads();

    // ---- cross-kgroup reduction (reuse syd: [16 g][12 r][64 c] = 48KB) ----
    float* red = (float*)syd;
#pragma unroll
    for (int r = 0; r < 12; r++) {
        float a0, a1, a2, a3;
        upk2(acc[r][0], a0, a1);
        upk2(acc[r][1], a2, a3);
        *(float4*)(red + gidx * 768 + r * 64 + c0) = make_float4(a0, a1, a2, a3);
    }
    __syncthreads();

#pragma unroll
    for (int h = 0; h < 3; h++) {
        const int o = h * 256 + tid;     // 0..767
        const int r = o >> 6, c = o & 63;
        const int row = row0 + r;
        if (row < TOT) {
            float sum = b1[c];
#pragma unroll
            for (int g = 0; g < 16; g++) sum += red[g * 768 + o];
            const int b = row / Nn, n = row - b * Nn;
            g_h[((size_t)b * Nn + n) * 64 + c] = sum;
        }
    }
}

// ======================================================================
// Kernel 2: depthwise 3x3 + 5x5 + 7x7, averaged, + identity -> g_sp
// Register-column sliding: per dx load 22-value column once, apply all
// (kernel, dy) taps from registers. LDS: 1328 -> ~240 per thread.
// ======================================================================
__global__ __launch_bounds__(256) void k2_dwconv(
    const float* __restrict__ w3, const float* __restrict__ b3,
    const float* __restrict__ w5, const float* __restrict__ b5,
    const float* __restrict__ w7, const float* __restrict__ b7)
{
    __shared__ __align__(16) float tile[38 * 38 * 4];
    __shared__ float wk[4 * 83];

    const int tid = threadIdx.x;
    const int cg = blockIdx.x;
    const int b = blockIdx.y;

    for (int i = tid; i < 4 * 83; i += 256) {
        int ch = i / 83, j = i - ch * 83;
        int c = cg * 4 + ch;
        float wv;
        if (j < 9)       wv = w3[c * 9 + j];
        else if (j < 34) wv = w5[c * 25 + (j - 9)];
        else             wv = w7[c * 49 + (j - 34)];
        wk[i] = wv;
    }

    const float* src = g_h + ((size_t)b * Nn + 1) * 64 + cg * 4;
    for (int idx = tid; idx < 38 * 38; idx += 256) {
        int rr = idx / 38, cc = idx - rr * 38;
        int gy = rr - 3, gxp = cc - 3;
        float4 val = make_float4(0.f, 0.f, 0.f, 0.f);
        if ((unsigned)gy < 32u && (unsigned)gxp < 32u)
            val = *(const float4*)(src + (size_t)(gy * 32 + gxp) * 64);
        *(float4*)&tile[idx * 4] = val;
    }
    __syncthreads();

    const int ch = tid & 3;
    const int col = (tid >> 2) & 31;
    const int row0 = (tid >> 7) * 16;

    float acc[16];
#pragma unroll
    for (int k = 0; k < 16; k++) acc[k] = 0.f;

    const float* wc = wk + ch * 83;

#pragma unroll
    for (int dx = 0; dx < 7; dx++) {           // actual dx offset = dx-3
        float v[22];
#pragma unroll
        for (int t = 0; t < 22; t++)
            v[t] = tile[((row0 + t) * 38 + col + dx) * 4 + ch];

        // 7x7: dy index 0..6 (offset dy-3); tap wc[34 + dy*7 + dx]
#pragma unroll
        for (int dy = 0; dy < 7; dy++) {
            float wv = wc[34 + dy * 7 + dx];
#pragma unroll
            for (int k = 0; k < 16; k++) acc[k] += v[k + dy] * wv;
        }
        // 5x5: |dx-3| <= 2
        if (dx >= 1 && dx <= 5) {
#pragma unroll
            for (int dy = 0; dy < 5; dy++) {
                float wv = wc[9 + dy * 5 + (dx - 1)];
#pragma unroll
                for (int k = 0; k < 16; k++) acc[k] += v[k + 1 + dy] * wv;
            }
        }
        // 3x3: |dx-3| <= 1
        if (dx >= 2 && dx <= 4) {
#pragma unroll
            for (int dy = 0; dy < 3; dy++) {
                float wv = wc[dy * 3 + (dx - 2)];
#pragma unroll
                for (int k = 0; k < 16; k++) acc[k] += v[k + 2 + dy] * wv;
            }
        }
    }

    const int c = cg * 4 + ch;
    const float bsum = (b3[c] + b5[c] + b7[c]) * (1.0f / 3.0f);
    float* dst = g_sp + ((size_t)b * 1024) * 64 + c;
    const float* ctr = tile + ((row0 + 3) * 38 + col + 3) * 4 + ch;
#pragma unroll
    for (int k = 0; k < 16; k++) {
        float o = acc[k] * (1.0f / 3.0f) + bsum + ctr[k * 152];
        dst[(size_t)((row0 + k) * 32 + col) * 64] = o;
    }
}

// ======================================================================
// Kernel 3: 1x1 proj + residual + exact GELU -> g_act (spatial tokens)
// f32x2 via position pairs: sp tile transposed to [ch][pos] so adjacent
// positions pack; per k: 4 broadcast LDS.64 + 1 LDS.32 + 4 FFMA2.
// ======================================================================
__global__ __launch_bounds__(256) void k3_proj_gelu(
    const float* __restrict__ pw, const float* __restrict__ pb)
{
    __shared__ float pws[64 * 65];                  // [out c][k], stride 65
    __shared__ __align__(16) float sspt[64 * 34];   // [k(ch)][pos], stride 34

    const int tid = threadIdx.x;
    const int b = blockIdx.x >> 5;
    const int pbase = (blockIdx.x & 31) * 32;

    for (int i = tid; i < 4096; i += 256)
        pws[(i >> 6) * 65 + (i & 63)] = pw[i];

    const float* src = g_sp + ((size_t)b * 1024 + pbase) * 64;
    for (int i = tid; i < 2048; i += 256) {
        int pos = i >> 6, cc = i & 63;
        sspt[cc * 34 + pos] = src[i];
    }
    __syncthreads();

    const int c = tid & 63;
    const int pg = tid >> 6;   // 4 groups x 8 positions
    unsigned long long acc2[4] = {0ull, 0ull, 0ull, 0ull};

    const float* wr = pws + c * 65;
    const float* yb = sspt + pg * 8;
#pragma unroll 8
    for (int k = 0; k < 64; k++) {
        float wv = wr[k];
        unsigned long long wd = pk2(wv, wv);
        const float* yk = yb + k * 34;
        fma2(acc2[0], *(const unsigned long long*)(yk + 0), wd);
        fma2(acc2[1], *(const unsigned long long*)(yk + 2), wd);
        fma2(acc2[2], *(const unsigned long long*)(yk + 4), wd);
        fma2(acc2[3], *(const unsigned long long*)(yk + 6), wd);
    }

    const float pbv = pb[c];
    float* dst = g_act + ((size_t)b * Nn + 1 + pbase + pg * 8) * 64 + c;
#pragma unroll
    for (int p = 0; p < 4; p++) {
        float a0, a1;
        upk2(acc2[p], a0, a1);
        float r0 = sspt[c * 34 + pg * 8 + 2 * p];
        float r1 = sspt[c * 34 + pg * 8 + 2 * p + 1];
        dst[(size_t)(2 * p) * 64] = gelu_exact(r0 + a0 + pbv);
        dst[(size_t)(2 * p + 1) * 64] = gelu_exact(r1 + a1 + pbv);
    }
}

// CLS token: gelu only
__global__ void k_cls_gelu() {
    int i = blockIdx.x * 256 + threadIdx.x;
    if (i < Bn * Cn) {
        int b = i >> 6, c = i & 63;
        size_t off = (size_t)b * Nn * 64 + c;
        g_act[off] = gelu_exact(g_h[off]);
    }
}

// ======================================================================
// Kernel 4: GEMM2 (g_act @ w2 + b2) + residual x -> out
// 256-col chunk of w2 resident in smem (64KB, loaded ONCE); streams 512
// rows in 8 subtiles of 64. Act L2 re-reads: 8x -> 4x. 2 CTAs/SM.
// ======================================================================
#define K4_SMEM (64*256*4 + 64*64*4)

__global__ __launch_bounds__(256, 2) void k4_gemm2(
    const float* __restrict__ x, const float* __restrict__ w2,
    const float* __restrict__ b2, float* __restrict__ out)
{
    extern __shared__ __align__(16) char sm4[];
    float* w2s = (float*)sm4;                      // [64 k][256 c]
    float* sga = (float*)(sm4 + 64 * 256 * 4);     // [64 k][64 r]

    const int tid = threadIdx.x;
    const int rb = blockIdx.x >> 2;                // row block (512 rows)
    const int co = (blockIdx.x & 3) * 256;         // col chunk
    const int rowbase = rb * 512;
    const int nsub = (TOT - rowbase < 512) ? ((TOT - rowbase) >> 6) : 8;

    // ---- load w2 chunk once: [64][256] = 64KB ----
#pragma unroll
    for (int i = 0; i < 16; i++) {
        int f = tid + 256 * i;                      // float4 index, 4096 total
        int k = f >> 6, c4 = f & 63;
        ((float4*)w2s)[f] = *(const float4*)(w2 + (size_t)k * 1024 + co + c4 * 4);
    }

    const int rg = tid >> 5;        // warp id -> rows rg*8..+7
    const int cw = tid & 31;        // cols cw*8..+7
    const int c0g = co + cw * 8;
    const float4 bv0 = *(const float4*)(b2 + c0g);
    const float4 bv1 = *(const float4*)(b2 + c0g + 4);

    const int lr = tid >> 2;        // load role: local row 0..63
    const int lq = tid & 3;         // k-quarter

    for (int s2 = 0; s2 < nsub; s2++) {
        __syncthreads();   // w2s ready (s2=0) / prev GEMM reads done

        // ---- load 64 act rows, transposed [k][r] ----
        {
            int row = rowbase + s2 * 64 + lr;
            int b = row / Nn, n = row - b * Nn;
            const float4* gp = (const float4*)(g_act + ((size_t)b * Nn + n) * 64 + lq * 16);
#pragma unroll
            for (int i = 0; i < 4; i++) {
                float4 g = gp[i];
                int k0 = lq * 16 + i * 4;
                sga[(k0 + 0) * 64 + lr] = g.x;
                sga[(k0 + 1) * 64 + lr] = g.y;
                sga[(k0 + 2) * 64 + lr] = g.z;
                sga[(k0 + 3) * 64 + lr] = g.w;
            }
        }
        __syncthreads();

        // ---- GEMM: 8 rows (4 natural pairs) x 8 cols ----
        unsigned long long acc[4][8];
#pragma unroll
        for (int p = 0; p < 4; p++)
#pragma unroll
            for (int j = 0; j < 8; j++) acc[p][j] = 0ull;

#pragma unroll 2
        for (int k = 0; k < 64; k++) {
            ulonglong2 yA = *(const ulonglong2*)(sga + (k << 6) + (rg << 3));
            ulonglong2 yB = *(const ulonglong2*)(sga + (k << 6) + (rg << 3) + 4);
            float4 wA = *(const float4*)(w2s + (k << 8) + (cw << 3));
            float4 wB = *(const float4*)(w2s + (k << 8) + (cw << 3) + 4);
            unsigned long long wd[8];
            wd[0] = pk2(wA.x, wA.x); wd[1] = pk2(wA.y, wA.y);
            wd[2] = pk2(wA.z, wA.z); wd[3] = pk2(wA.w, wA.w);
            wd[4] = pk2(wB.x, wB.x); wd[5] = pk2(wB.y, wB.y);
            wd[6] = pk2(wB.z, wB.z); wd[7] = pk2(wB.w, wB.w);
#pragma unroll
            for (int j = 0; j < 8; j++) {
                fma2(acc[0][j], yA.x, wd[j]);
                fma2(acc[1][j], yA.y, wd[j]);
                fma2(acc[2][j], yB.x, wd[j]);
                fma2(acc[3][j], yB.y, wd[j]);
            }
        }

        // ---- epilogue: + b2 + x residual -> out (N,B,D layout) ----
#pragma unroll
        for (int p = 0; p < 4; p++) {
            int rowe = rowbase + s2 * 64 + rg * 8 + 2 * p;
            float ae[8], ao[8];
#pragma unroll
            for (int j = 0; j < 8; j++) upk2(acc[p][j], ae[j], ao[j]);

            int b = rowe / Nn, n = rowe - b * Nn;
            size_t offe = ((size_t)(n * Bn + b) << 10) + c0g;
            float4 x0 = *(const float4*)(x + offe);
            float4 x1 = *(const float4*)(x + offe + 4);
            *(float4*)(out + offe) = make_float4(x0.x + bv0.x + ae[0], x0.y + bv0.y + ae[1],
                                                 x0.z + bv0.z + ae[2], x0.w + bv0.w + ae[3]);
            *(float4*)(out + offe + 4) = make_float4(x1.x + bv1.x + ae[4], x1.y + bv1.y + ae[5],
                                                     x1.z + bv1.z + ae[6], x1.w + bv1.w + ae[7]);
            int rowo = rowe + 1;
            int b2i = rowo / Nn, n2 = rowo - b2i * Nn;
            size_t offo = ((size_t)(n2 * Bn + b2i) << 10) + c0g;
            float4 x2 = *(const float4*)(x + offo);
            float4 x3 = *(const float4*)(x + offo + 4);
            *(float4*)(out + offo) = make_float4(x2.x + bv0.x + ao[0], x2.y + bv0.y + ao[1],
                                                 x2.z + bv0.z + ao[2], x2.w + bv0.w + ao[3]);
            *(float4*)(out + offo + 4) = make_float4(x3.x + bv1.x + ao[4], x3.y + bv1.y + ao[5],
                                                     x3.z + bv1.z + ao[6], x3.w + bv1.w + ao[7]);
        }
    }
}

// ======================================================================
extern "C" void kernel_launch(void* const* d_in, const int* in_sizes, int n_in,
                              void* d_out, int out_size)
{
    (void)in_sizes; (void)n_in; (void)out_size;
    const float* x     = (const float*)d_in[0];
    const float* ln_w  = (const float*)d_in[1];
    const float* ln_b  = (const float*)d_in[2];
    const float* gamma = (const float*)d_in[3];
    const float* gmx   = (const float*)d_in[4];
    const float* w1    = (const float*)d_in[5];
    const float* b1    = (const float*)d_in[6];
    const float* w2    = (const float*)d_in[7];
    const float* b2    = (const float*)d_in[8];
    const float* dw3w  = (const float*)d_in[9];
    const float* dw3b  = (const float*)d_in[10];
    const float* dw5w  = (const float*)d_in[11];
    const float* dw5b  = (const float*)d_in[12];
    const float* dw7w  = (const float*)d_in[13];
    const float* dw7b  = (const float*)d_in[14];
    const float* projw = (const float*)d_in[15];
    const float* projb = (const float*)d_in[16];
    float* out = (float*)d_out;

    cudaFuncSetAttribute(k1_ln_gemm1, cudaFuncAttributeMaxDynamicSharedMemorySize, K1_SMEM);
    cudaFuncSetAttribute(k4_gemm2,    cudaFuncAttributeMaxDynamicSharedMemorySize, K4_SMEM);

    // 65600 rows -> 5467 blocks x 12 rows (last block: 8 valid rows)
    k1_ln_gemm1<<<5467, 256, K1_SMEM>>>(x, ln_w, ln_b, gamma, gmx, w1, b1);
    k2_dwconv<<<dim3(16, 64), 256>>>(dw3w, dw3b, dw5w, dw5b, dw7w, dw7b);
    k_cls_gelu<<<16, 256>>>();
    k3_proj_gelu<<<2048, 256>>>(projw, projb);
    // 129 row-blocks of 512 rows (last has 64) x 4 col-chunks
    k4_gemm2<<<129 * 4, 256, K4_SMEM>>>(x, w2, b2, out);
}